// round 12
// baseline (speedup 1.0000x reference)
#include <cuda_runtime.h>
#include <cuda_bf16.h>
#include <cstdint>

#define B_    32
#define C_    512
#define HW_   1024
#define C8_   64
#define WR_   640     // 64 q + 64 k + 512 v rows

#if defined(__CUDA_ARCH__) && defined(__CUDA_ARCH_FEAT_SM103_ALL)
#define HAS_TCGEN05 1
#else
#define HAS_TCGEN05 0
#endif

// ---------------------------------------------------------------------------
// Scratch (device globals)
// ---------------------------------------------------------------------------
__device__ __nv_bfloat16 g_xT_hi[(size_t)B_ * HW_ * C_];   // [b][i][c]
__device__ __nv_bfloat16 g_xT_lo[(size_t)B_ * HW_ * C_];
__device__ __nv_bfloat16 g_w_hi [(size_t)WR_ * C_];        // [o][c]
__device__ __nv_bfloat16 g_w_lo [(size_t)WR_ * C_];
__device__ __nv_bfloat16 g_qT_hi[(size_t)B_ * HW_ * C8_];  // [b][i][c8]
__device__ __nv_bfloat16 g_qT_lo[(size_t)B_ * HW_ * C8_];
__device__ __nv_bfloat16 g_kT_hi[(size_t)B_ * HW_ * C8_];
__device__ __nv_bfloat16 g_kT_lo[(size_t)B_ * HW_ * C8_];
__device__ __nv_bfloat16 g_v_hi [(size_t)B_ * C_ * HW_];   // [c][j]
__device__ __nv_bfloat16 g_v_lo [(size_t)B_ * C_ * HW_];

// ---------------------------------------------------------------------------
// Helpers
// ---------------------------------------------------------------------------
__device__ __forceinline__ uint32_t smem_u32(const void* p) {
    uint32_t a;
    asm("{ .reg .u64 t; cvta.to.shared.u64 t, %1; cvt.u32.u64 %0, t; }" : "=r"(a) : "l"(p));
    return a;
}
__device__ __forceinline__ uint32_t elect_one_pred() {
    uint32_t p;
    asm volatile("{\n\t.reg .pred p;\n\telect.sync _|p, 0xFFFFFFFF;\n\tselp.b32 %0, 1, 0, p;\n\t}" : "=r"(p));
    return p;
}
#define SMEM_SWIZZLE_128B(off) ((off) ^ (((off) >> 3) & 0x70))

__device__ __forceinline__ void cp16(uint32_t dst, const void* src) {
    asm volatile("cp.async.cg.shared.global [%0], [%1], 16;" :: "r"(dst), "l"(src));
}
__device__ __forceinline__ void cp_commit() {
    asm volatile("cp.async.commit_group;" ::: "memory");
}

// pack two fp32 -> bf16x2 (hi) and residual bf16x2 (lo)
__device__ __forceinline__ void split2(float a, float b, uint32_t& hi, uint32_t& lo) {
    asm("cvt.rn.bf16x2.f32 %0, %1, %2;" : "=r"(hi) : "f"(b), "f"(a));
    float fa = __uint_as_float(hi << 16);
    float fb = __uint_as_float(hi & 0xFFFF0000u);
    asm("cvt.rn.bf16x2.f32 %0, %1, %2;" : "=r"(lo) : "f"(b - fb), "f"(a - fa));
}
__device__ __forceinline__ void split1(float v, __nv_bfloat16& h, __nv_bfloat16& l) {
    h = __float2bfloat16(v);
    l = __float2bfloat16(v - __bfloat162float(h));
}
__device__ __forceinline__ float recon(const __nv_bfloat16* h, const __nv_bfloat16* l, size_t i) {
    return __bfloat162float(h[i]) + __bfloat162float(l[i]);
}

static constexpr uint64_t DESC_BASE_SW128 =
    (uint64_t(2) << 61) | (uint64_t(1) << 46) | (uint64_t(64) << 32) | (uint64_t(1) << 16);
__device__ __forceinline__ uint64_t make_desc(uint32_t addr) {
    return DESC_BASE_SW128 | ((uint64_t)(addr >> 4) & 0x3FFF);
}
__device__ __forceinline__ void mbar_init(uint32_t a, uint32_t cnt) {
    asm volatile("mbarrier.init.shared.b64 [%0], %1;" :: "r"(a), "r"(cnt) : "memory");
}
__device__ __forceinline__ void mbar_inval(uint32_t a) {
    asm volatile("mbarrier.inval.shared.b64 [%0];" :: "r"(a) : "memory");
}
__device__ __forceinline__ void mbar_wait(uint32_t a, uint32_t parity) {
    asm volatile(
        "{\n\t.reg .pred P;\n\t"
        "WL_%=:\n\t"
        "mbarrier.try_wait.parity.acquire.cta.shared::cta.b64 P, [%0], %1, 0x989680;\n\t"
        "@P bra.uni WD_%=;\n\t"
        "bra.uni WL_%=;\n\t"
        "WD_%=:\n\t}"
        :: "r"(a), "r"(parity) : "memory");
}

static constexpr uint32_t IDESC_128x128 =
    (1u << 4) | (1u << 7) | (1u << 10) | ((128u / 8) << 17) | ((128u / 16) << 24);
static constexpr uint32_t IDESC_128x256 =
    (1u << 4) | (1u << 7) | (1u << 10) | ((256u / 8) << 17) | ((128u / 16) << 24);

static constexpr int TILE_BYTES  = 16384;           // 128 rows x 128B
static constexpr int QKV_STAGE   = 4 * TILE_BYTES;  // Ahi,Alo,Bhi,Blo (64KB)
static constexpr int QKV_SMEM    = 1024 + 2 * QKV_STAGE;        // 132096
static constexpr int EN_SMEM     = 1024 + 2 * TILE_BYTES + 4 * 32768;   // 164864
static constexpr int OUT_STAGE   = 2 * 32768 + 2 * TILE_BYTES;  // A(256r) hi/lo + B hi/lo = 96KB
static constexpr int OUT_SMEM    = 1024 + 2 * OUT_STAGE;        // 197632

#if HAS_TCGEN05
__device__ __forceinline__ void mma_f16_ss(uint32_t d, uint64_t da, uint64_t db,
                                           uint32_t idesc, uint32_t en) {
    asm volatile(
        "{\n\t.reg .pred p;\n\tsetp.ne.u32 p, %4, 0;\n\t"
        "tcgen05.mma.cta_group::1.kind::f16 [%0], %1, %2, %3, {%5,%5,%5,%5}, p;\n\t}"
        :: "r"(d), "l"(da), "l"(db), "r"(idesc), "r"(en), "r"(0u) : "memory");
}
__device__ __forceinline__ void tc_commit(uint32_t mbar) {
    asm volatile("tcgen05.commit.cta_group::1.mbarrier::arrive::one.shared::cluster.b64 [%0];"
                 :: "r"(mbar) : "memory");
}
__device__ __forceinline__ void tc_alloc(uint32_t smem_addr, uint32_t cols) {
    asm volatile("tcgen05.alloc.cta_group::1.sync.aligned.shared::cta.b32 [%0], %1;"
                 :: "r"(smem_addr), "r"(cols) : "memory");
}
__device__ __forceinline__ void tc_dealloc(uint32_t tmem, uint32_t cols) {
    asm volatile("tcgen05.relinquish_alloc_permit.cta_group::1.sync.aligned;" ::: "memory");
    asm volatile("tcgen05.dealloc.cta_group::1.sync.aligned.b32 %0, %1;" :: "r"(tmem), "r"(cols));
}
#define TCGEN05_LD_32X32B_X32(r, tmem_addr) \
    asm volatile( \
        "tcgen05.ld.sync.aligned.32x32b.x32.b32 " \
        "{%0, %1, %2, %3, %4, %5, %6, %7, " \
        " %8, %9, %10, %11, %12, %13, %14, %15, " \
        " %16, %17, %18, %19, %20, %21, %22, %23, " \
        " %24, %25, %26, %27, %28, %29, %30, %31}, [%32];" \
        : "=r"((r)[0]),  "=r"((r)[1]),  "=r"((r)[2]),  "=r"((r)[3]), \
          "=r"((r)[4]),  "=r"((r)[5]),  "=r"((r)[6]),  "=r"((r)[7]), \
          "=r"((r)[8]),  "=r"((r)[9]),  "=r"((r)[10]), "=r"((r)[11]), \
          "=r"((r)[12]), "=r"((r)[13]), "=r"((r)[14]), "=r"((r)[15]), \
          "=r"((r)[16]), "=r"((r)[17]), "=r"((r)[18]), "=r"((r)[19]), \
          "=r"((r)[20]), "=r"((r)[21]), "=r"((r)[22]), "=r"((r)[23]), \
          "=r"((r)[24]), "=r"((r)[25]), "=r"((r)[26]), "=r"((r)[27]), \
          "=r"((r)[28]), "=r"((r)[29]), "=r"((r)[30]), "=r"((r)[31]) \
        : "r"(tmem_addr))
#endif

// ---------------------------------------------------------------------------
// Prep 1: transpose + split x [b][c][i] fp32 -> xT_hi/lo [b][i][c] bf16
// Vectorized epilogue: uint4 (8 bf16) stores.
// ---------------------------------------------------------------------------
__global__ void xsplit_kernel(const float* __restrict__ x)
{
    __shared__ float t[32][33];
    const int b  = blockIdx.z;
    const int i0 = blockIdx.x * 32;
    const int c0 = blockIdx.y * 32;
    const int tx = threadIdx.x, ty = threadIdx.y;
    const int tid = ty * 32 + tx;

#pragma unroll
    for (int j = 0; j < 4; ++j)
        t[ty + 8 * j][tx] = x[((size_t)b * C_ + c0 + ty + 8 * j) * HW_ + i0 + tx];
    __syncthreads();

    if (tid < 128) {
        const int il = tid >> 2;            // 0..31
        const int cs = (tid & 3) * 8;       // 0,8,16,24
        uint32_t hi[4], lo[4];
#pragma unroll
        for (int p = 0; p < 4; ++p)
            split2(t[cs + 2 * p][il], t[cs + 2 * p + 1][il], hi[p], lo[p]);
        const size_t idx = ((size_t)b * HW_ + i0 + il) * C_ + c0 + cs;
        *reinterpret_cast<uint4*>(g_xT_hi + idx) = make_uint4(hi[0], hi[1], hi[2], hi[3]);
        *reinterpret_cast<uint4*>(g_xT_lo + idx) = make_uint4(lo[0], lo[1], lo[2], lo[3]);
    }
}

// ---------------------------------------------------------------------------
// Prep 2: split weights into combined [640][512] bf16 hi/lo
// ---------------------------------------------------------------------------
__global__ void wsplit_kernel(const float* __restrict__ wq,
                              const float* __restrict__ wk,
                              const float* __restrict__ wv)
{
    const int idx = blockIdx.x * 256 + threadIdx.x;   // < 640*512
    const int o = idx >> 9;
    const int c = idx & 511;
    float v;
    if (o < 64)        v = wq[(size_t)o * C_ + c];
    else if (o < 128)  v = wk[(size_t)(o - 64) * C_ + c];
    else               v = wv[(size_t)(o - 128) * C_ + c];
    __nv_bfloat16 h, l;
    split1(v, h, l);
    g_w_hi[idx] = h;
    g_w_lo[idx] = l;
}

// ---------------------------------------------------------------------------
// Kernel: QKV projection on tcgen05 (bf16x3), cp.async 2-stage prefetch.
// ---------------------------------------------------------------------------
__global__ __launch_bounds__(256) void qkv_tc_kernel(
    const float* __restrict__ bq, const float* __restrict__ bk,
    const float* __restrict__ bv)
{
    extern __shared__ char smem[];
    const int tid = threadIdx.x;
    const int b   = blockIdx.z;
    const int mt  = blockIdx.y;
    const int m0  = mt * 128;
    const int n0  = blockIdx.x * 128;

#if HAS_TCGEN05
    const uint32_t sb = smem_u32(smem);
    const __nv_bfloat16* whb = g_w_hi + (size_t)m0 * C_;
    const __nv_bfloat16* wlb = g_w_lo + (size_t)m0 * C_;
    const __nv_bfloat16* xhb = g_xT_hi + ((size_t)b * HW_ + n0) * C_;
    const __nv_bfloat16* xlb = g_xT_lo + ((size_t)b * HW_ + n0) * C_;

    auto copies = [&](int k, int s) {
        const int k0 = k * 64;
        const uint32_t base = sb + 1024 + s * QKV_STAGE;
#pragma unroll
        for (int i = 0; i < 4; ++i) {
            const int u = tid + i * 256;
            const int r = u >> 3;
            const int c = (u & 7) * 8;
            const uint32_t sw = SMEM_SWIZZLE_128B((uint32_t)(r * 128 + c * 2));
            cp16(base + sw,                  whb + (size_t)r * C_ + k0 + c);
            cp16(base + TILE_BYTES + sw,     wlb + (size_t)r * C_ + k0 + c);
            cp16(base + 2 * TILE_BYTES + sw, xhb + (size_t)r * C_ + k0 + c);
            cp16(base + 3 * TILE_BYTES + sw, xlb + (size_t)r * C_ + k0 + c);
        }
        cp_commit();
    };

    copies(0, 0);
    if (tid < 32) tc_alloc(sb, 128u);
    if (tid == 0) { mbar_init(sb + 8, 1); mbar_init(sb + 16, 1); }
    __syncthreads();
    const uint32_t tmem = *reinterpret_cast<volatile uint32_t*>(smem);

    for (int k = 0; k < 8; ++k) {
        const int s = k & 1;
        if (k < 7) {
            const int j = k + 1;
            if (j >= 2) mbar_wait(sb + 8 + (j & 1) * 8, (uint32_t)(((j >> 1) - 1) & 1));
            copies(j, j & 1);
            asm volatile("cp.async.wait_group 1;" ::: "memory");
        } else {
            asm volatile("cp.async.wait_group 0;" ::: "memory");
        }
        __syncthreads();
        asm volatile("fence.proxy.async.shared::cta;" ::: "memory");

        if (tid < 32 && elect_one_pred()) {
            const uint32_t su = sb + 1024 + s * QKV_STAGE;
            const uint64_t dAh = make_desc(su);
            const uint64_t dAl = make_desc(su + TILE_BYTES);
            const uint64_t dBh = make_desc(su + 2 * TILE_BYTES);
            const uint64_t dBl = make_desc(su + 3 * TILE_BYTES);
#pragma unroll
            for (int ks = 0; ks < 4; ++ks) {
                const uint32_t en0 = (k == 0 && ks == 0) ? 0u : 1u;
                mma_f16_ss(tmem, dAh + ks * 2, dBh + ks * 2, IDESC_128x128, en0);
                mma_f16_ss(tmem, dAh + ks * 2, dBl + ks * 2, IDESC_128x128, 1u);
                mma_f16_ss(tmem, dAl + ks * 2, dBh + ks * 2, IDESC_128x128, 1u);
            }
            tc_commit(sb + 8 + s * 8);
        }
    }
    mbar_wait(sb + 8, 1u);
    mbar_wait(sb + 16, 1u);
    asm volatile("tcgen05.fence::after_thread_sync;" ::: "memory");
    __syncthreads();

    if (mt == 0) {
        float* ep = reinterpret_cast<float*>(smem + 1024);
        for (int cb = 0; cb < 128; cb += 32) {
            if (tid < 128) {
                uint32_t d[32];
                TCGEN05_LD_32X32B_X32(d, tmem + cb);
                asm volatile("tcgen05.wait::ld.sync.aligned;" ::: "memory");
                const float bias = (tid < 64) ? bq[tid] : bk[tid - 64];
#pragma unroll
                for (int c = 0; c < 32; ++c)
                    ep[tid * 33 + c] = __uint_as_float(d[c]) + bias;
            }
            __syncthreads();
            const int il = tid >> 3;
            const int ob = (tid & 7) * 8;
            {   // q
                uint32_t hi[4], lo[4];
#pragma unroll
                for (int e = 0; e < 4; ++e)
                    split2(ep[(ob + 2 * e) * 33 + il], ep[(ob + 2 * e + 1) * 33 + il], hi[e], lo[e]);
                const size_t qi = ((size_t)b * HW_ + n0 + cb + il) * C8_ + ob;
                *reinterpret_cast<uint4*>(g_qT_hi + qi) = make_uint4(hi[0], hi[1], hi[2], hi[3]);
                *reinterpret_cast<uint4*>(g_qT_lo + qi) = make_uint4(lo[0], lo[1], lo[2], lo[3]);
            }
            {   // k
                uint32_t hi[4], lo[4];
#pragma unroll
                for (int e = 0; e < 4; ++e)
                    split2(ep[(64 + ob + 2 * e) * 33 + il], ep[(64 + ob + 2 * e + 1) * 33 + il], hi[e], lo[e]);
                const size_t ki = ((size_t)b * HW_ + n0 + cb + il) * C8_ + ob;
                *reinterpret_cast<uint4*>(g_kT_hi + ki) = make_uint4(hi[0], hi[1], hi[2], hi[3]);
                *reinterpret_cast<uint4*>(g_kT_lo + ki) = make_uint4(lo[0], lo[1], lo[2], lo[3]);
            }
            __syncthreads();
        }
    } else {
        if (tid < 128) {
            const int c = m0 - 128 + tid;
            const float bias = bv[c];
            for (int cb = 0; cb < 128; cb += 32) {
                uint32_t d[32];
                TCGEN05_LD_32X32B_X32(d, tmem + cb);
                asm volatile("tcgen05.wait::ld.sync.aligned;" ::: "memory");
                uint32_t hi[16], lo[16];
#pragma unroll
                for (int e = 0; e < 16; ++e)
                    split2(__uint_as_float(d[2 * e]) + bias, __uint_as_float(d[2 * e + 1]) + bias,
                           hi[e], lo[e]);
                const size_t base = ((size_t)b * C_ + c) * HW_ + n0 + cb;
                uint4* dh = reinterpret_cast<uint4*>(g_v_hi + base);
                uint4* dl = reinterpret_cast<uint4*>(g_v_lo + base);
#pragma unroll
                for (int e = 0; e < 4; ++e) {
                    dh[e] = make_uint4(hi[4 * e], hi[4 * e + 1], hi[4 * e + 2], hi[4 * e + 3]);
                    dl[e] = make_uint4(lo[4 * e], lo[4 * e + 1], lo[4 * e + 2], lo[4 * e + 3]);
                }
            }
        }
    }
    __syncthreads();
    if (tid == 0) { mbar_inval(sb + 8); mbar_inval(sb + 16); }
    if (tid < 32) tc_dealloc(tmem, 128u);
#else
    for (int e = tid; e < 128 * 128; e += 256) {
        const int ml = e >> 7, nl = e & 127;
        const int o = m0 + ml, i = n0 + nl;
        float acc = 0.f;
        for (int c = 0; c < C_; ++c)
            acc += recon(g_w_hi, g_w_lo, (size_t)o * C_ + c) *
                   recon(g_xT_hi, g_xT_lo, ((size_t)b * HW_ + i) * C_ + c);
        __nv_bfloat16 h, l;
        if (o < 64) {
            split1(acc + bq[o], h, l);
            const size_t qi = ((size_t)b * HW_ + i) * C8_ + o;
            g_qT_hi[qi] = h; g_qT_lo[qi] = l;
        } else if (o < 128) {
            split1(acc + bk[o - 64], h, l);
            const size_t ki = ((size_t)b * HW_ + i) * C8_ + (o - 64);
            g_kT_hi[ki] = h; g_kT_lo[ki] = l;
        } else {
            split1(acc + bv[o - 128], h, l);
            const size_t vi = ((size_t)b * C_ + (o - 128)) * HW_ + i;
            g_v_hi[vi] = h; g_v_lo[vi] = l;
        }
    }
#endif
}

// ---------------------------------------------------------------------------
// Kernel: energy on tcgen05 (bf16x3). Two N=256 tiles per CTA sharing the
// A (q) tile. E[i,j] = sum_c q[i,c] k[j,c]. M=128 (i), per-CTA N=512 (j).
// ---------------------------------------------------------------------------
__global__ __launch_bounds__(256) void energy_tc_kernel(float* __restrict__ att)
{
    extern __shared__ char smem[];
    const int tid = threadIdx.x;
    const int b  = blockIdx.z;
    const int m0 = blockIdx.y * 128;   // i
    const int n0 = blockIdx.x * 512;   // j

#if HAS_TCGEN05
    const uint32_t sb  = smem_u32(smem);
    const uint32_t SAh = sb + 1024;
    const uint32_t SAl = SAh + TILE_BYTES;
    const uint32_t SB0h = SAl + TILE_BYTES;
    const uint32_t SB0l = SB0h + 32768;
    const uint32_t SB1h = SB0l + 32768;
    const uint32_t SB1l = SB1h + 32768;

    const __nv_bfloat16* qh = g_qT_hi + ((size_t)b * HW_ + m0) * C8_;
    const __nv_bfloat16* ql = g_qT_lo + ((size_t)b * HW_ + m0) * C8_;
    const __nv_bfloat16* kh = g_kT_hi + ((size_t)b * HW_ + n0) * C8_;
    const __nv_bfloat16* kl = g_kT_lo + ((size_t)b * HW_ + n0) * C8_;

#pragma unroll
    for (int i = 0; i < 4; ++i) {
        const int u = tid + i * 256;
        const int r = u >> 3;
        const int c = (u & 7) * 8;
        const uint32_t sw = SMEM_SWIZZLE_128B((uint32_t)(r * 128 + c * 2));
        cp16(SAh + sw, qh + (size_t)r * C8_ + c);
        cp16(SAl + sw, ql + (size_t)r * C8_ + c);
    }
#pragma unroll
    for (int i = 0; i < 8; ++i) {
        const int u = tid + i * 256;
        const int r = u >> 3;
        const int c = (u & 7) * 8;
        const uint32_t sw = SMEM_SWIZZLE_128B((uint32_t)(r * 128 + c * 2));
        cp16(SB0h + sw, kh + (size_t)r * C8_ + c);
        cp16(SB0l + sw, kl + (size_t)r * C8_ + c);
    }
    cp_commit();
#pragma unroll
    for (int i = 0; i < 8; ++i) {
        const int u = tid + i * 256;
        const int r = (u >> 3) + 256;
        const int c = (u & 7) * 8;
        const uint32_t sw = SMEM_SWIZZLE_128B((uint32_t)((r - 256) * 128 + c * 2));
        cp16(SB1h + sw, kh + (size_t)r * C8_ + c);
        cp16(SB1l + sw, kl + (size_t)r * C8_ + c);
    }
    cp_commit();

    if (tid < 32) tc_alloc(sb, 512u);
    if (tid == 0) { mbar_init(sb + 8, 1); mbar_init(sb + 16, 1); }
    __syncthreads();
    const uint32_t tmem = *reinterpret_cast<volatile uint32_t*>(smem);

    const uint64_t dAh = make_desc(SAh);
    const uint64_t dAl = make_desc(SAl);

    asm volatile("cp.async.wait_group 1;" ::: "memory");
    __syncthreads();
    asm volatile("fence.proxy.async.shared::cta;" ::: "memory");
    if (tid < 32 && elect_one_pred()) {
        const uint64_t dBh = make_desc(SB0h);
        const uint64_t dBl = make_desc(SB0l);
#pragma unroll
        for (int ks = 0; ks < 4; ++ks) {
            mma_f16_ss(tmem, dAh + ks * 2, dBh + ks * 2, IDESC_128x256, ks == 0 ? 0u : 1u);
            mma_f16_ss(tmem, dAh + ks * 2, dBl + ks * 2, IDESC_128x256, 1u);
            mma_f16_ss(tmem, dAl + ks * 2, dBh + ks * 2, IDESC_128x256, 1u);
        }
        tc_commit(sb + 8);
    }
    asm volatile("cp.async.wait_group 0;" ::: "memory");
    __syncthreads();
    asm volatile("fence.proxy.async.shared::cta;" ::: "memory");
    if (tid < 32 && elect_one_pred()) {
        const uint64_t dBh = make_desc(SB1h);
        const uint64_t dBl = make_desc(SB1l);
#pragma unroll
        for (int ks = 0; ks < 4; ++ks) {
            mma_f16_ss(tmem + 256, dAh + ks * 2, dBh + ks * 2, IDESC_128x256, ks == 0 ? 0u : 1u);
            mma_f16_ss(tmem + 256, dAh + ks * 2, dBl + ks * 2, IDESC_128x256, 1u);
            mma_f16_ss(tmem + 256, dAl + ks * 2, dBh + ks * 2, IDESC_128x256, 1u);
        }
        tc_commit(sb + 16);
    }

#pragma unroll
    for (int t = 0; t < 2; ++t) {
        mbar_wait(sb + 8 + t * 8, 0u);
        asm volatile("tcgen05.fence::after_thread_sync;" ::: "memory");
        if (tid < 128) {
            float* row = att + ((size_t)b * HW_ + m0 + tid) * HW_ + n0 + t * 256;
            for (int cb = 0; cb < 256; cb += 32) {
                uint32_t d[32];
                TCGEN05_LD_32X32B_X32(d, tmem + t * 256 + cb);
                asm volatile("tcgen05.wait::ld.sync.aligned;" ::: "memory");
                float4* dst = reinterpret_cast<float4*>(row + cb);
#pragma unroll
                for (int e = 0; e < 8; ++e)
                    dst[e] = make_float4(__uint_as_float(d[4 * e]),     __uint_as_float(d[4 * e + 1]),
                                         __uint_as_float(d[4 * e + 2]), __uint_as_float(d[4 * e + 3]));
            }
        }
    }
    __syncthreads();
    if (tid == 0) { mbar_inval(sb + 8); mbar_inval(sb + 16); }
    if (tid < 32) tc_dealloc(tmem, 512u);
#else
    for (int e = tid; e < 128 * 512; e += 256) {
        const int ml = e >> 9, nl = e & 511;
        float acc = 0.f;
        for (int c = 0; c < C8_; ++c)
            acc += recon(g_qT_hi, g_qT_lo, ((size_t)b * HW_ + m0 + ml) * C8_ + c) *
                   recon(g_kT_hi, g_kT_lo, ((size_t)b * HW_ + n0 + nl) * C8_ + c);
        att[((size_t)b * HW_ + m0 + ml) * HW_ + n0 + nl] = acc;
    }
#endif
}

// ---------------------------------------------------------------------------
// Softmax (in place, pure fp32 — no bf16 emission).
// ---------------------------------------------------------------------------
__global__ __launch_bounds__(256) void softmax_kernel(float* __restrict__ att)
{
    const size_t row = blockIdx.x;
    float4* p = reinterpret_cast<float4*>(att + row * HW_);
    float4 v = p[threadIdx.x];

    __shared__ float red[8];
    const int lid = threadIdx.x & 31;
    const int wid = threadIdx.x >> 5;

    float m = fmaxf(fmaxf(v.x, v.y), fmaxf(v.z, v.w));
#pragma unroll
    for (int off = 16; off; off >>= 1)
        m = fmaxf(m, __shfl_xor_sync(0xFFFFFFFFu, m, off));
    if (lid == 0) red[wid] = m;
    __syncthreads();
    m = red[0];
#pragma unroll
    for (int w = 1; w < 8; ++w) m = fmaxf(m, red[w]);
    __syncthreads();

    v.x = __expf(v.x - m);
    v.y = __expf(v.y - m);
    v.z = __expf(v.z - m);
    v.w = __expf(v.w - m);

    float s = v.x + v.y + v.z + v.w;
#pragma unroll
    for (int off = 16; off; off >>= 1)
        s += __shfl_xor_sync(0xFFFFFFFFu, s, off);
    if (lid == 0) red[wid] = s;
    __syncthreads();
    s = red[0];
#pragma unroll
    for (int w = 1; w < 8; ++w) s += red[w];

    const float inv = 1.0f / s;
    v.x *= inv; v.y *= inv; v.z *= inv; v.w *= inv;
    p[threadIdx.x] = v;
}

// ---------------------------------------------------------------------------
// Kernel: out GEMM on tcgen05 (bf16x3), M=256 (2 m-slices), N=128.
// A (v) pre-split via cp.async; B (att) read fp32 + split inline.
// D[c,i] = sum_j V[c,j] Att[i,j]; rgb = g*D + x; hha_out = g*D + hha.
// ---------------------------------------------------------------------------
__global__ __launch_bounds__(256)
void out_tc_kernel(const float* __restrict__ att, const float* __restrict__ x,
                   const float* __restrict__ hha, const float* __restrict__ gamma,
                   float* __restrict__ rgb, float* __restrict__ hhaout)
{
    extern __shared__ char smem[];
    const int tid = threadIdx.x;
    const int b  = blockIdx.z;
    const int m0 = blockIdx.y * 256;   // channels (grid.y == 2)
    const int n0 = blockIdx.x * 128;   // pixels

#if HAS_TCGEN05
    const uint32_t sb = smem_u32(smem);
    const __nv_bfloat16* vh = g_v_hi + ((size_t)b * C_  + m0) * HW_;  // 256 rows
    const __nv_bfloat16* vl = g_v_lo + ((size_t)b * C_  + m0) * HW_;
    const float* att_b = att + ((size_t)b * HW_ + n0) * HW_;          // 128 rows fp32

    auto copies = [&](int k, int s) {
        const int k0 = k * 64;
        const uint32_t base = sb + 1024 + s * OUT_STAGE;
        // A (v): 256 rows hi/lo via cp.async
#pragma unroll
        for (int i = 0; i < 8; ++i) {
            const int u = tid + i * 256;
            const int r = u >> 3;
            const int c = (u & 7) * 8;
            const uint32_t sw = SMEM_SWIZZLE_128B((uint32_t)(r * 128 + c * 2));
            cp16(base + sw,         vh + (size_t)r * HW_ + k0 + c);
            cp16(base + 32768 + sw, vl + (size_t)r * HW_ + k0 + c);
        }
        cp_commit();
        // B (att): 128 rows x 64 fp32 -> split inline to hi/lo bf16 swizzled
        {
            const int r  = tid >> 1;           // 0..127 (pixel row i)
            const int h0 = (tid & 1) * 32;     // 0 or 32 (j offset)
            const float* src = att_b + (size_t)r * HW_ + k0 + h0;
            float4 f[8];
#pragma unroll
            for (int e = 0; e < 8; ++e)
                f[e] = *reinterpret_cast<const float4*>(src + e * 4);
            uint32_t hi[16], lo[16];
#pragma unroll
            for (int e = 0; e < 8; ++e) {
                split2(f[e].x, f[e].y, hi[2 * e],     lo[2 * e]);
                split2(f[e].z, f[e].w, hi[2 * e + 1], lo[2 * e + 1]);
            }
#pragma unroll
            for (int e = 0; e < 4; ++e) {
                const uint32_t sw = SMEM_SWIZZLE_128B((uint32_t)(r * 128 + (h0 + e * 8) * 2));
                *reinterpret_cast<uint4*>(smem + (base - sb) + 65536 + sw) =
                    make_uint4(hi[4 * e], hi[4 * e + 1], hi[4 * e + 2], hi[4 * e + 3]);
                *reinterpret_cast<uint4*>(smem + (base - sb) + 65536 + TILE_BYTES + sw) =
                    make_uint4(lo[4 * e], lo[4 * e + 1], lo[4 * e + 2], lo[4 * e + 3]);
            }
        }
    };

    copies(0, 0);
    if (tid < 32) tc_alloc(sb, 256u);
    if (tid == 0) { mbar_init(sb + 8, 1); mbar_init(sb + 16, 1); }
    __syncthreads();
    const uint32_t tmem = *reinterpret_cast<volatile uint32_t*>(smem);

    for (int k = 0; k < 16; ++k) {
        const int s = k & 1;
        if (k < 15) {
            const int j = k + 1;
            if (j >= 2) mbar_wait(sb + 8 + (j & 1) * 8, (uint32_t)(((j >> 1) - 1) & 1));
            copies(j, j & 1);
            asm volatile("cp.async.wait_group 1;" ::: "memory");
        } else {
            asm volatile("cp.async.wait_group 0;" ::: "memory");
        }
        __syncthreads();
        asm volatile("fence.proxy.async.shared::cta;" ::: "memory");

        if (tid < 32 && elect_one_pred()) {
            const uint32_t base = sb + 1024 + s * OUT_STAGE;
            const uint64_t dAh = make_desc(base);
            const uint64_t dAl = make_desc(base + 32768);
            const uint64_t dBh = make_desc(base + 65536);
            const uint64_t dBl = make_desc(base + 65536 + TILE_BYTES);
#pragma unroll
            for (int s2 = 0; s2 < 2; ++s2) {
                const uint64_t ao = (uint64_t)s2 * 1024;   // +16KB in 16B units
                const uint32_t dd = tmem + s2 * 128;
#pragma unroll
                for (int ks = 0; ks < 4; ++ks) {
                    const uint32_t en0 = (k == 0 && ks == 0) ? 0u : 1u;
                    mma_f16_ss(dd, dAh + ao + ks * 2, dBh + ks * 2, IDESC_128x128, en0);
                    mma_f16_ss(dd, dAh + ao + ks * 2, dBl + ks * 2, IDESC_128x128, 1u);
                    mma_f16_ss(dd, dAl + ao + ks * 2, dBh + ks * 2, IDESC_128x128, 1u);
                }
            }
            tc_commit(sb + 8 + s * 8);
        }
    }
    mbar_wait(sb + 8, 1u);
    mbar_wait(sb + 16, 1u);
    asm volatile("tcgen05.fence::after_thread_sync;" ::: "memory");
    __syncthreads();

    const float g = gamma[0];
    if (tid < 128) {
#pragma unroll
        for (int s2 = 0; s2 < 2; ++s2) {
            const size_t base = ((size_t)b * C_ + m0 + s2 * 128 + tid) * HW_ + n0;
            for (int cb = 0; cb < 128; cb += 32) {
                uint32_t d[32];
                TCGEN05_LD_32X32B_X32(d, tmem + s2 * 128 + cb);
                asm volatile("tcgen05.wait::ld.sync.aligned;" ::: "memory");
#pragma unroll
                for (int e = 0; e < 8; ++e) {
                    const size_t gb = base + cb + e * 4;
                    float4 x4 = *reinterpret_cast<const float4*>(x + gb);
                    float4 h4 = *reinterpret_cast<const float4*>(hha + gb);
                    const float o0 = g * __uint_as_float(d[4 * e]);
                    const float o1 = g * __uint_as_float(d[4 * e + 1]);
                    const float o2 = g * __uint_as_float(d[4 * e + 2]);
                    const float o3 = g * __uint_as_float(d[4 * e + 3]);
                    *reinterpret_cast<float4*>(rgb + gb) =
                        make_float4(o0 + x4.x, o1 + x4.y, o2 + x4.z, o3 + x4.w);
                    *reinterpret_cast<float4*>(hhaout + gb) =
                        make_float4(o0 + h4.x, o1 + h4.y, o2 + h4.z, o3 + h4.w);
                }
            }
        }
    }
    __syncthreads();
    if (tid == 0) { mbar_inval(sb + 8); mbar_inval(sb + 16); }
    if (tid < 32) tc_dealloc(tmem, 256u);
#else
    const float g = gamma[0];
    for (int e = tid; e < 256 * 128; e += 256) {
        const int ml = e >> 7, nl = e & 127;
        float acc = 0.f;
        for (int j = 0; j < HW_; ++j)
            acc += recon(g_v_hi, g_v_lo, ((size_t)b * C_ + m0 + ml) * HW_ + j) *
                   att[((size_t)b * HW_ + n0 + nl) * HW_ + j];
        const size_t gb = ((size_t)b * C_ + m0 + ml) * HW_ + n0 + nl;
        rgb[gb]    = g * acc + x[gb];
        hhaout[gb] = g * acc + hha[gb];
    }
#endif
}

// ---------------------------------------------------------------------------
extern "C" void kernel_launch(void* const* d_in, const int* in_sizes, int n_in,
                              void* d_out, int out_size)
{
    const float* x     = (const float*)d_in[0];
    const float* hha   = (const float*)d_in[1];
    const float* wq    = (const float*)d_in[2];
    const float* bq    = (const float*)d_in[3];
    const float* wk    = (const float*)d_in[4];
    const float* bk    = (const float*)d_in[5];
    const float* wv    = (const float*)d_in[6];
    const float* bv    = (const float*)d_in[7];
    const float* gamma = (const float*)d_in[8];

    float* att    = (float*)d_out;                         // [32,1024,1024]
    float* rgb    = att + (size_t)B_ * HW_ * HW_;          // [32,512,32,32]
    float* hhaout = rgb + (size_t)B_ * C_ * HW_;           // [32,512,32,32]

    static bool attr_set = false;
    if (!attr_set) {
        cudaFuncSetAttribute(qkv_tc_kernel,    cudaFuncAttributeMaxDynamicSharedMemorySize, QKV_SMEM);
        cudaFuncSetAttribute(energy_tc_kernel, cudaFuncAttributeMaxDynamicSharedMemorySize, EN_SMEM);
        cudaFuncSetAttribute(out_tc_kernel,    cudaFuncAttributeMaxDynamicSharedMemorySize, OUT_SMEM);
        attr_set = true;
    }

    xsplit_kernel   <<<dim3(32, 16, 32), dim3(32, 8)>>>(x);
    wsplit_kernel   <<<WR_ * C_ / 256, 256>>>(wq, wk, wv);
    qkv_tc_kernel   <<<dim3(8, 5, 32), 256, QKV_SMEM>>>(bq, bk, bv);
    energy_tc_kernel<<<dim3(2, 8, 32), 256, EN_SMEM>>>(att);
    softmax_kernel  <<<B_ * HW_, 256>>>(att);
    out_tc_kernel   <<<dim3(8, 2, 32), 256, OUT_SMEM>>>(att, x, hha, gamma, rgb, hhaout);
}

// round 13
// speedup vs baseline: 1.2148x; 1.2148x over previous
#include <cuda_runtime.h>
#include <cuda_bf16.h>
#include <cstdint>

#define B_    32
#define C_    512
#define HW_   1024
#define C8_   64
#define WR_   640     // 64 q + 64 k + 512 v rows

#if defined(__CUDA_ARCH__) && defined(__CUDA_ARCH_FEAT_SM103_ALL)
#define HAS_TCGEN05 1
#else
#define HAS_TCGEN05 0
#endif

// ---------------------------------------------------------------------------
// Scratch (device globals)
// ---------------------------------------------------------------------------
__device__ __nv_bfloat16 g_xT_hi[(size_t)B_ * HW_ * C_];   // [b][i][c]
__device__ __nv_bfloat16 g_xT_lo[(size_t)B_ * HW_ * C_];
__device__ __nv_bfloat16 g_w_hi [(size_t)WR_ * C_];        // [o][c]
__device__ __nv_bfloat16 g_w_lo [(size_t)WR_ * C_];
__device__ __nv_bfloat16 g_qT_hi[(size_t)B_ * HW_ * C8_];  // [b][i][c8]
__device__ __nv_bfloat16 g_qT_lo[(size_t)B_ * HW_ * C8_];
__device__ __nv_bfloat16 g_kT_hi[(size_t)B_ * HW_ * C8_];
__device__ __nv_bfloat16 g_kT_lo[(size_t)B_ * HW_ * C8_];
__device__ __nv_bfloat16 g_v_hi [(size_t)B_ * C_ * HW_];   // [c][j]
__device__ __nv_bfloat16 g_v_lo [(size_t)B_ * C_ * HW_];
__device__ __nv_bfloat16 g_att_hi[(size_t)B_ * HW_ * HW_]; // [i][j]
__device__ __nv_bfloat16 g_att_lo[(size_t)B_ * HW_ * HW_];

// ---------------------------------------------------------------------------
// Helpers
// ---------------------------------------------------------------------------
__device__ __forceinline__ uint32_t smem_u32(const void* p) {
    uint32_t a;
    asm("{ .reg .u64 t; cvta.to.shared.u64 t, %1; cvt.u32.u64 %0, t; }" : "=r"(a) : "l"(p));
    return a;
}
__device__ __forceinline__ uint32_t elect_one_pred() {
    uint32_t p;
    asm volatile("{\n\t.reg .pred p;\n\telect.sync _|p, 0xFFFFFFFF;\n\tselp.b32 %0, 1, 0, p;\n\t}" : "=r"(p));
    return p;
}
#define SMEM_SWIZZLE_128B(off) ((off) ^ (((off) >> 3) & 0x70))

__device__ __forceinline__ void cp16(uint32_t dst, const void* src) {
    asm volatile("cp.async.cg.shared.global [%0], [%1], 16;" :: "r"(dst), "l"(src));
}
__device__ __forceinline__ void cp_commit() {
    asm volatile("cp.async.commit_group;" ::: "memory");
}

// pack two fp32 -> bf16x2 (hi) and residual bf16x2 (lo)
__device__ __forceinline__ void split2(float a, float b, uint32_t& hi, uint32_t& lo) {
    asm("cvt.rn.bf16x2.f32 %0, %1, %2;" : "=r"(hi) : "f"(b), "f"(a));
    float fa = __uint_as_float(hi << 16);
    float fb = __uint_as_float(hi & 0xFFFF0000u);
    asm("cvt.rn.bf16x2.f32 %0, %1, %2;" : "=r"(lo) : "f"(b - fb), "f"(a - fa));
}
__device__ __forceinline__ void split1(float v, __nv_bfloat16& h, __nv_bfloat16& l) {
    h = __float2bfloat16(v);
    l = __float2bfloat16(v - __bfloat162float(h));
}
__device__ __forceinline__ float recon(const __nv_bfloat16* h, const __nv_bfloat16* l, size_t i) {
    return __bfloat162float(h[i]) + __bfloat162float(l[i]);
}

static constexpr uint64_t DESC_BASE_SW128 =
    (uint64_t(2) << 61) | (uint64_t(1) << 46) | (uint64_t(64) << 32) | (uint64_t(1) << 16);
__device__ __forceinline__ uint64_t make_desc(uint32_t addr) {
    return DESC_BASE_SW128 | ((uint64_t)(addr >> 4) & 0x3FFF);
}
__device__ __forceinline__ void mbar_init(uint32_t a, uint32_t cnt) {
    asm volatile("mbarrier.init.shared.b64 [%0], %1;" :: "r"(a), "r"(cnt) : "memory");
}
__device__ __forceinline__ void mbar_inval(uint32_t a) {
    asm volatile("mbarrier.inval.shared.b64 [%0];" :: "r"(a) : "memory");
}
__device__ __forceinline__ void mbar_wait(uint32_t a, uint32_t parity) {
    asm volatile(
        "{\n\t.reg .pred P;\n\t"
        "WL_%=:\n\t"
        "mbarrier.try_wait.parity.acquire.cta.shared::cta.b64 P, [%0], %1, 0x989680;\n\t"
        "@P bra.uni WD_%=;\n\t"
        "bra.uni WL_%=;\n\t"
        "WD_%=:\n\t}"
        :: "r"(a), "r"(parity) : "memory");
}

static constexpr uint32_t IDESC_128x128 =
    (1u << 4) | (1u << 7) | (1u << 10) | ((128u / 8) << 17) | ((128u / 16) << 24);
static constexpr uint32_t IDESC_128x256 =
    (1u << 4) | (1u << 7) | (1u << 10) | ((256u / 8) << 17) | ((128u / 16) << 24);

static constexpr int TILE_BYTES  = 16384;           // 128 rows x 128B
static constexpr int QKV_STAGE   = 4 * TILE_BYTES;  // Ahi,Alo,Bhi,Blo (64KB)
static constexpr int QKV_SMEM    = 1024 + 3 * QKV_STAGE;        // 197632 (3-stage)
static constexpr int EN_SMEM     = 1024 + 2 * TILE_BYTES + 4 * 32768;   // 164864
static constexpr int OUT_STAGE   = 2 * 32768 + 2 * TILE_BYTES;  // A(256r) hi/lo + B hi/lo = 96KB
static constexpr int OUT_SMEM    = 1024 + 2 * OUT_STAGE;        // 197632

#if HAS_TCGEN05
__device__ __forceinline__ void mma_f16_ss(uint32_t d, uint64_t da, uint64_t db,
                                           uint32_t idesc, uint32_t en) {
    asm volatile(
        "{\n\t.reg .pred p;\n\tsetp.ne.u32 p, %4, 0;\n\t"
        "tcgen05.mma.cta_group::1.kind::f16 [%0], %1, %2, %3, {%5,%5,%5,%5}, p;\n\t}"
        :: "r"(d), "l"(da), "l"(db), "r"(idesc), "r"(en), "r"(0u) : "memory");
}
__device__ __forceinline__ void tc_commit(uint32_t mbar) {
    asm volatile("tcgen05.commit.cta_group::1.mbarrier::arrive::one.shared::cluster.b64 [%0];"
                 :: "r"(mbar) : "memory");
}
__device__ __forceinline__ void tc_alloc(uint32_t smem_addr, uint32_t cols) {
    asm volatile("tcgen05.alloc.cta_group::1.sync.aligned.shared::cta.b32 [%0], %1;"
                 :: "r"(smem_addr), "r"(cols) : "memory");
}
__device__ __forceinline__ void tc_dealloc(uint32_t tmem, uint32_t cols) {
    asm volatile("tcgen05.relinquish_alloc_permit.cta_group::1.sync.aligned;" ::: "memory");
    asm volatile("tcgen05.dealloc.cta_group::1.sync.aligned.b32 %0, %1;" :: "r"(tmem), "r"(cols));
}
#define TCGEN05_LD_32X32B_X32(r, tmem_addr) \
    asm volatile( \
        "tcgen05.ld.sync.aligned.32x32b.x32.b32 " \
        "{%0, %1, %2, %3, %4, %5, %6, %7, " \
        " %8, %9, %10, %11, %12, %13, %14, %15, " \
        " %16, %17, %18, %19, %20, %21, %22, %23, " \
        " %24, %25, %26, %27, %28, %29, %30, %31}, [%32];" \
        : "=r"((r)[0]),  "=r"((r)[1]),  "=r"((r)[2]),  "=r"((r)[3]), \
          "=r"((r)[4]),  "=r"((r)[5]),  "=r"((r)[6]),  "=r"((r)[7]), \
          "=r"((r)[8]),  "=r"((r)[9]),  "=r"((r)[10]), "=r"((r)[11]), \
          "=r"((r)[12]), "=r"((r)[13]), "=r"((r)[14]), "=r"((r)[15]), \
          "=r"((r)[16]), "=r"((r)[17]), "=r"((r)[18]), "=r"((r)[19]), \
          "=r"((r)[20]), "=r"((r)[21]), "=r"((r)[22]), "=r"((r)[23]), \
          "=r"((r)[24]), "=r"((r)[25]), "=r"((r)[26]), "=r"((r)[27]), \
          "=r"((r)[28]), "=r"((r)[29]), "=r"((r)[30]), "=r"((r)[31]) \
        : "r"(tmem_addr))
#endif

// ---------------------------------------------------------------------------
// Prep 1: transpose + split x (vectorized epilogue)
// ---------------------------------------------------------------------------
__global__ void xsplit_kernel(const float* __restrict__ x)
{
    __shared__ float t[32][33];
    const int b  = blockIdx.z;
    const int i0 = blockIdx.x * 32;
    const int c0 = blockIdx.y * 32;
    const int tx = threadIdx.x, ty = threadIdx.y;
    const int tid = ty * 32 + tx;

#pragma unroll
    for (int j = 0; j < 4; ++j)
        t[ty + 8 * j][tx] = x[((size_t)b * C_ + c0 + ty + 8 * j) * HW_ + i0 + tx];
    __syncthreads();

    if (tid < 128) {
        const int il = tid >> 2;            // 0..31
        const int cs = (tid & 3) * 8;       // 0,8,16,24
        uint32_t hi[4], lo[4];
#pragma unroll
        for (int p = 0; p < 4; ++p)
            split2(t[cs + 2 * p][il], t[cs + 2 * p + 1][il], hi[p], lo[p]);
        const size_t idx = ((size_t)b * HW_ + i0 + il) * C_ + c0 + cs;
        *reinterpret_cast<uint4*>(g_xT_hi + idx) = make_uint4(hi[0], hi[1], hi[2], hi[3]);
        *reinterpret_cast<uint4*>(g_xT_lo + idx) = make_uint4(lo[0], lo[1], lo[2], lo[3]);
    }
}

// ---------------------------------------------------------------------------
// Prep 2: split weights into combined [640][512] bf16 hi/lo
// ---------------------------------------------------------------------------
__global__ void wsplit_kernel(const float* __restrict__ wq,
                              const float* __restrict__ wk,
                              const float* __restrict__ wv)
{
    const int idx = blockIdx.x * 256 + threadIdx.x;   // < 640*512
    const int o = idx >> 9;
    const int c = idx & 511;
    float v;
    if (o < 64)        v = wq[(size_t)o * C_ + c];
    else if (o < 128)  v = wk[(size_t)(o - 64) * C_ + c];
    else               v = wv[(size_t)(o - 128) * C_ + c];
    __nv_bfloat16 h, l;
    split1(v, h, l);
    g_w_hi[idx] = h;
    g_w_lo[idx] = l;
}

// ---------------------------------------------------------------------------
// Kernel: QKV projection on tcgen05 (bf16x3), cp.async 3-stage prefetch.
// ---------------------------------------------------------------------------
__global__ __launch_bounds__(256) void qkv_tc_kernel(
    const float* __restrict__ bq, const float* __restrict__ bk,
    const float* __restrict__ bv)
{
    extern __shared__ char smem[];
    const int tid = threadIdx.x;
    const int b   = blockIdx.z;
    const int mt  = blockIdx.y;
    const int m0  = mt * 128;
    const int n0  = blockIdx.x * 128;

#if HAS_TCGEN05
    const uint32_t sb = smem_u32(smem);
    const __nv_bfloat16* whb = g_w_hi + (size_t)m0 * C_;
    const __nv_bfloat16* wlb = g_w_lo + (size_t)m0 * C_;
    const __nv_bfloat16* xhb = g_xT_hi + ((size_t)b * HW_ + n0) * C_;
    const __nv_bfloat16* xlb = g_xT_lo + ((size_t)b * HW_ + n0) * C_;

    auto copies = [&](int k, int s) {
        const int k0 = k * 64;
        const uint32_t base = sb + 1024 + s * QKV_STAGE;
#pragma unroll
        for (int i = 0; i < 4; ++i) {
            const int u = tid + i * 256;
            const int r = u >> 3;
            const int c = (u & 7) * 8;
            const uint32_t sw = SMEM_SWIZZLE_128B((uint32_t)(r * 128 + c * 2));
            cp16(base + sw,                  whb + (size_t)r * C_ + k0 + c);
            cp16(base + TILE_BYTES + sw,     wlb + (size_t)r * C_ + k0 + c);
            cp16(base + 2 * TILE_BYTES + sw, xhb + (size_t)r * C_ + k0 + c);
            cp16(base + 3 * TILE_BYTES + sw, xlb + (size_t)r * C_ + k0 + c);
        }
        cp_commit();
    };

    copies(0, 0);
    copies(1, 1);
    if (tid < 32) tc_alloc(sb, 128u);
    if (tid == 0) { mbar_init(sb + 8, 1); mbar_init(sb + 16, 1); mbar_init(sb + 24, 1); }
    __syncthreads();
    const uint32_t tmem = *reinterpret_cast<volatile uint32_t*>(smem);

    for (int k = 0; k < 8; ++k) {
        const int s = k % 3;
        const int j = k + 2;
        if (j < 8) {
            if (j >= 3) mbar_wait(sb + 8 + (j % 3) * 8, (uint32_t)((j / 3 - 1) & 1));
            copies(j, j % 3);
            asm volatile("cp.async.wait_group 2;" ::: "memory");
        } else if (k == 6) {
            asm volatile("cp.async.wait_group 1;" ::: "memory");
        } else {
            asm volatile("cp.async.wait_group 0;" ::: "memory");
        }
        __syncthreads();
        asm volatile("fence.proxy.async.shared::cta;" ::: "memory");

        if (tid < 32 && elect_one_pred()) {
            const uint32_t su = sb + 1024 + s * QKV_STAGE;
            const uint64_t dAh = make_desc(su);
            const uint64_t dAl = make_desc(su + TILE_BYTES);
            const uint64_t dBh = make_desc(su + 2 * TILE_BYTES);
            const uint64_t dBl = make_desc(su + 3 * TILE_BYTES);
#pragma unroll
            for (int ks = 0; ks < 4; ++ks) {
                const uint32_t en0 = (k == 0 && ks == 0) ? 0u : 1u;
                mma_f16_ss(tmem, dAh + ks * 2, dBh + ks * 2, IDESC_128x128, en0);
                mma_f16_ss(tmem, dAh + ks * 2, dBl + ks * 2, IDESC_128x128, 1u);
                mma_f16_ss(tmem, dAl + ks * 2, dBh + ks * 2, IDESC_128x128, 1u);
            }
            tc_commit(sb + 8 + s * 8);
        }
    }
    // commits per stage: s0 at k=0,3,6 (3 -> parity 0); s1 at k=1,4,7 (3 -> 0); s2 at k=2,5 (2 -> 1)
    mbar_wait(sb + 8, 0u);
    mbar_wait(sb + 16, 0u);
    mbar_wait(sb + 24, 1u);
    asm volatile("tcgen05.fence::after_thread_sync;" ::: "memory");
    __syncthreads();

    if (mt == 0) {
        float* ep = reinterpret_cast<float*>(smem + 1024);
        for (int cb = 0; cb < 128; cb += 32) {
            if (tid < 128) {
                uint32_t d[32];
                TCGEN05_LD_32X32B_X32(d, tmem + cb);
                asm volatile("tcgen05.wait::ld.sync.aligned;" ::: "memory");
                const float bias = (tid < 64) ? bq[tid] : bk[tid - 64];
#pragma unroll
                for (int c = 0; c < 32; ++c)
                    ep[tid * 33 + c] = __uint_as_float(d[c]) + bias;
            }
            __syncthreads();
            const int il = tid >> 3;
            const int ob = (tid & 7) * 8;
            {   // q
                uint32_t hi[4], lo[4];
#pragma unroll
                for (int e = 0; e < 4; ++e)
                    split2(ep[(ob + 2 * e) * 33 + il], ep[(ob + 2 * e + 1) * 33 + il], hi[e], lo[e]);
                const size_t qi = ((size_t)b * HW_ + n0 + cb + il) * C8_ + ob;
                *reinterpret_cast<uint4*>(g_qT_hi + qi) = make_uint4(hi[0], hi[1], hi[2], hi[3]);
                *reinterpret_cast<uint4*>(g_qT_lo + qi) = make_uint4(lo[0], lo[1], lo[2], lo[3]);
            }
            {   // k
                uint32_t hi[4], lo[4];
#pragma unroll
                for (int e = 0; e < 4; ++e)
                    split2(ep[(64 + ob + 2 * e) * 33 + il], ep[(64 + ob + 2 * e + 1) * 33 + il], hi[e], lo[e]);
                const size_t ki = ((size_t)b * HW_ + n0 + cb + il) * C8_ + ob;
                *reinterpret_cast<uint4*>(g_kT_hi + ki) = make_uint4(hi[0], hi[1], hi[2], hi[3]);
                *reinterpret_cast<uint4*>(g_kT_lo + ki) = make_uint4(lo[0], lo[1], lo[2], lo[3]);
            }
            __syncthreads();
        }
    } else {
        if (tid < 128) {
            const int c = m0 - 128 + tid;
            const float bias = bv[c];
            for (int cb = 0; cb < 128; cb += 32) {
                uint32_t d[32];
                TCGEN05_LD_32X32B_X32(d, tmem + cb);
                asm volatile("tcgen05.wait::ld.sync.aligned;" ::: "memory");
                uint32_t hi[16], lo[16];
#pragma unroll
                for (int e = 0; e < 16; ++e)
                    split2(__uint_as_float(d[2 * e]) + bias, __uint_as_float(d[2 * e + 1]) + bias,
                           hi[e], lo[e]);
                const size_t base = ((size_t)b * C_ + c) * HW_ + n0 + cb;
                uint4* dh = reinterpret_cast<uint4*>(g_v_hi + base);
                uint4* dl = reinterpret_cast<uint4*>(g_v_lo + base);
#pragma unroll
                for (int e = 0; e < 4; ++e) {
                    dh[e] = make_uint4(hi[4 * e], hi[4 * e + 1], hi[4 * e + 2], hi[4 * e + 3]);
                    dl[e] = make_uint4(lo[4 * e], lo[4 * e + 1], lo[4 * e + 2], lo[4 * e + 3]);
                }
            }
        }
    }
    __syncthreads();
    if (tid == 0) { mbar_inval(sb + 8); mbar_inval(sb + 16); mbar_inval(sb + 24); }
    if (tid < 32) tc_dealloc(tmem, 128u);
#else
    for (int e = tid; e < 128 * 128; e += 256) {
        const int ml = e >> 7, nl = e & 127;
        const int o = m0 + ml, i = n0 + nl;
        float acc = 0.f;
        for (int c = 0; c < C_; ++c)
            acc += recon(g_w_hi, g_w_lo, (size_t)o * C_ + c) *
                   recon(g_xT_hi, g_xT_lo, ((size_t)b * HW_ + i) * C_ + c);
        __nv_bfloat16 h, l;
        if (o < 64) {
            split1(acc + bq[o], h, l);
            const size_t qi = ((size_t)b * HW_ + i) * C8_ + o;
            g_qT_hi[qi] = h; g_qT_lo[qi] = l;
        } else if (o < 128) {
            split1(acc + bk[o - 64], h, l);
            const size_t ki = ((size_t)b * HW_ + i) * C8_ + (o - 64);
            g_kT_hi[ki] = h; g_kT_lo[ki] = l;
        } else {
            split1(acc + bv[o - 128], h, l);
            const size_t vi = ((size_t)b * C_ + (o - 128)) * HW_ + i;
            g_v_hi[vi] = h; g_v_lo[vi] = l;
        }
    }
#endif
}

// ---------------------------------------------------------------------------
// Kernel: energy on tcgen05 (bf16x3). Two N=256 tiles per CTA sharing the
// A (q) tile. E[i,j] = sum_c q[i,c] k[j,c]. M=128 (i), per-CTA N=512 (j).
// ---------------------------------------------------------------------------
__global__ __launch_bounds__(256) void energy_tc_kernel(float* __restrict__ att)
{
    extern __shared__ char smem[];
    const int tid = threadIdx.x;
    const int b  = blockIdx.z;
    const int m0 = blockIdx.y * 128;   // i
    const int n0 = blockIdx.x * 512;   // j

#if HAS_TCGEN05
    const uint32_t sb  = smem_u32(smem);
    const uint32_t SAh = sb + 1024;
    const uint32_t SAl = SAh + TILE_BYTES;
    const uint32_t SB0h = SAl + TILE_BYTES;
    const uint32_t SB0l = SB0h + 32768;
    const uint32_t SB1h = SB0l + 32768;
    const uint32_t SB1l = SB1h + 32768;

    const __nv_bfloat16* qh = g_qT_hi + ((size_t)b * HW_ + m0) * C8_;
    const __nv_bfloat16* ql = g_qT_lo + ((size_t)b * HW_ + m0) * C8_;
    const __nv_bfloat16* kh = g_kT_hi + ((size_t)b * HW_ + n0) * C8_;
    const __nv_bfloat16* kl = g_kT_lo + ((size_t)b * HW_ + n0) * C8_;

#pragma unroll
    for (int i = 0; i < 4; ++i) {
        const int u = tid + i * 256;
        const int r = u >> 3;
        const int c = (u & 7) * 8;
        const uint32_t sw = SMEM_SWIZZLE_128B((uint32_t)(r * 128 + c * 2));
        cp16(SAh + sw, qh + (size_t)r * C8_ + c);
        cp16(SAl + sw, ql + (size_t)r * C8_ + c);
    }
#pragma unroll
    for (int i = 0; i < 8; ++i) {
        const int u = tid + i * 256;
        const int r = u >> 3;
        const int c = (u & 7) * 8;
        const uint32_t sw = SMEM_SWIZZLE_128B((uint32_t)(r * 128 + c * 2));
        cp16(SB0h + sw, kh + (size_t)r * C8_ + c);
        cp16(SB0l + sw, kl + (size_t)r * C8_ + c);
    }
    cp_commit();
#pragma unroll
    for (int i = 0; i < 8; ++i) {
        const int u = tid + i * 256;
        const int r = (u >> 3) + 256;
        const int c = (u & 7) * 8;
        const uint32_t sw = SMEM_SWIZZLE_128B((uint32_t)((r - 256) * 128 + c * 2));
        cp16(SB1h + sw, kh + (size_t)r * C8_ + c);
        cp16(SB1l + sw, kl + (size_t)r * C8_ + c);
    }
    cp_commit();

    if (tid < 32) tc_alloc(sb, 512u);
    if (tid == 0) { mbar_init(sb + 8, 1); mbar_init(sb + 16, 1); }
    __syncthreads();
    const uint32_t tmem = *reinterpret_cast<volatile uint32_t*>(smem);

    const uint64_t dAh = make_desc(SAh);
    const uint64_t dAl = make_desc(SAl);

    asm volatile("cp.async.wait_group 1;" ::: "memory");
    __syncthreads();
    asm volatile("fence.proxy.async.shared::cta;" ::: "memory");
    if (tid < 32 && elect_one_pred()) {
        const uint64_t dBh = make_desc(SB0h);
        const uint64_t dBl = make_desc(SB0l);
#pragma unroll
        for (int ks = 0; ks < 4; ++ks) {
            mma_f16_ss(tmem, dAh + ks * 2, dBh + ks * 2, IDESC_128x256, ks == 0 ? 0u : 1u);
            mma_f16_ss(tmem, dAh + ks * 2, dBl + ks * 2, IDESC_128x256, 1u);
            mma_f16_ss(tmem, dAl + ks * 2, dBh + ks * 2, IDESC_128x256, 1u);
        }
        tc_commit(sb + 8);
    }
    asm volatile("cp.async.wait_group 0;" ::: "memory");
    __syncthreads();
    asm volatile("fence.proxy.async.shared::cta;" ::: "memory");
    if (tid < 32 && elect_one_pred()) {
        const uint64_t dBh = make_desc(SB1h);
        const uint64_t dBl = make_desc(SB1l);
#pragma unroll
        for (int ks = 0; ks < 4; ++ks) {
            mma_f16_ss(tmem + 256, dAh + ks * 2, dBh + ks * 2, IDESC_128x256, ks == 0 ? 0u : 1u);
            mma_f16_ss(tmem + 256, dAh + ks * 2, dBl + ks * 2, IDESC_128x256, 1u);
            mma_f16_ss(tmem + 256, dAl + ks * 2, dBh + ks * 2, IDESC_128x256, 1u);
        }
        tc_commit(sb + 16);
    }

#pragma unroll
    for (int t = 0; t < 2; ++t) {
        mbar_wait(sb + 8 + t * 8, 0u);
        asm volatile("tcgen05.fence::after_thread_sync;" ::: "memory");
        if (tid < 128) {
            float* row = att + ((size_t)b * HW_ + m0 + tid) * HW_ + n0 + t * 256;
            for (int cb = 0; cb < 256; cb += 32) {
                uint32_t d[32];
                TCGEN05_LD_32X32B_X32(d, tmem + t * 256 + cb);
                asm volatile("tcgen05.wait::ld.sync.aligned;" ::: "memory");
                float4* dst = reinterpret_cast<float4*>(row + cb);
#pragma unroll
                for (int e = 0; e < 8; ++e)
                    dst[e] = make_float4(__uint_as_float(d[4 * e]),     __uint_as_float(d[4 * e + 1]),
                                         __uint_as_float(d[4 * e + 2]), __uint_as_float(d[4 * e + 3]));
            }
        }
    }
    __syncthreads();
    if (tid == 0) { mbar_inval(sb + 8); mbar_inval(sb + 16); }
    if (tid < 32) tc_dealloc(tmem, 512u);
#else
    for (int e = tid; e < 128 * 512; e += 256) {
        const int ml = e >> 9, nl = e & 511;
        float acc = 0.f;
        for (int c = 0; c < C8_; ++c)
            acc += recon(g_qT_hi, g_qT_lo, ((size_t)b * HW_ + m0 + ml) * C8_ + c) *
                   recon(g_kT_hi, g_kT_lo, ((size_t)b * HW_ + n0 + nl) * C8_ + c);
        att[((size_t)b * HW_ + m0 + ml) * HW_ + n0 + nl] = acc;
    }
#endif
}

// ---------------------------------------------------------------------------
// Softmax (in place) + emit att_hi/att_lo bf16 for the out GEMM.
// ---------------------------------------------------------------------------
__global__ __launch_bounds__(256) void softmax_kernel(float* __restrict__ att)
{
    const size_t row = blockIdx.x;
    float4* p = reinterpret_cast<float4*>(att + row * HW_);
    float4 v = p[threadIdx.x];

    __shared__ float red[8];
    const int lid = threadIdx.x & 31;
    const int wid = threadIdx.x >> 5;

    float m = fmaxf(fmaxf(v.x, v.y), fmaxf(v.z, v.w));
#pragma unroll
    for (int off = 16; off; off >>= 1)
        m = fmaxf(m, __shfl_xor_sync(0xFFFFFFFFu, m, off));
    if (lid == 0) red[wid] = m;
    __syncthreads();
    m = red[0];
#pragma unroll
    for (int w = 1; w < 8; ++w) m = fmaxf(m, red[w]);
    __syncthreads();

    v.x = __expf(v.x - m);
    v.y = __expf(v.y - m);
    v.z = __expf(v.z - m);
    v.w = __expf(v.w - m);

    float s = v.x + v.y + v.z + v.w;
#pragma unroll
    for (int off = 16; off; off >>= 1)
        s += __shfl_xor_sync(0xFFFFFFFFu, s, off);
    if (lid == 0) red[wid] = s;
    __syncthreads();
    s = red[0];
#pragma unroll
    for (int w = 1; w < 8; ++w) s += red[w];

    const float inv = 1.0f / s;
    v.x *= inv; v.y *= inv; v.z *= inv; v.w *= inv;
    p[threadIdx.x] = v;

    uint32_t h0, l0, h1, l1;
    split2(v.x, v.y, h0, l0);
    split2(v.z, v.w, h1, l1);
    const size_t e = row * HW_ + (size_t)threadIdx.x * 4;
    *reinterpret_cast<uint2*>(g_att_hi + e) = make_uint2(h0, h1);
    *reinterpret_cast<uint2*>(g_att_lo + e) = make_uint2(l0, l1);
}

// ---------------------------------------------------------------------------
// Kernel: out GEMM on tcgen05 (bf16x3), M=256 (2 m-slices), N=128.
// cp.async prefetch pipeline; direct TMEM->GMEM epilogue. (R10 structure)
// ---------------------------------------------------------------------------
__global__ __launch_bounds__(256)
void out_tc_kernel(const float* __restrict__ x,
                   const float* __restrict__ hha, const float* __restrict__ gamma,
                   float* __restrict__ rgb, float* __restrict__ hhaout)
{
    extern __shared__ char smem[];
    const int tid = threadIdx.x;
    const int b  = blockIdx.z;
    const int m0 = blockIdx.y * 256;   // channels (grid.y == 2)
    const int n0 = blockIdx.x * 128;   // pixels

#if HAS_TCGEN05
    const uint32_t sb = smem_u32(smem);
    const __nv_bfloat16* vh = g_v_hi   + ((size_t)b * C_  + m0) * HW_;  // 256 rows
    const __nv_bfloat16* vl = g_v_lo   + ((size_t)b * C_  + m0) * HW_;
    const __nv_bfloat16* ah = g_att_hi + ((size_t)b * HW_ + n0) * HW_;  // 128 rows
    const __nv_bfloat16* al = g_att_lo + ((size_t)b * HW_ + n0) * HW_;

    auto copies = [&](int k, int s) {
        const int k0 = k * 64;
        const uint32_t base = sb + 1024 + s * OUT_STAGE;
#pragma unroll
        for (int i = 0; i < 8; ++i) {
            const int u = tid + i * 256;
            const int r = u >> 3;
            const int c = (u & 7) * 8;
            const uint32_t sw = SMEM_SWIZZLE_128B((uint32_t)(r * 128 + c * 2));
            cp16(base + sw,         vh + (size_t)r * HW_ + k0 + c);
            cp16(base + 32768 + sw, vl + (size_t)r * HW_ + k0 + c);
        }
#pragma unroll
        for (int i = 0; i < 4; ++i) {
            const int u = tid + i * 256;
            const int r = u >> 3;
            const int c = (u & 7) * 8;
            const uint32_t sw = SMEM_SWIZZLE_128B((uint32_t)(r * 128 + c * 2));
            cp16(base + 65536 + sw, ah + (size_t)r * HW_ + k0 + c);
            cp16(base + 65536 + TILE_BYTES + sw, al + (size_t)r * HW_ + k0 + c);
        }
        cp_commit();
    };

    copies(0, 0);
    if (tid < 32) tc_alloc(sb, 256u);
    if (tid == 0) { mbar_init(sb + 8, 1); mbar_init(sb + 16, 1); }
    __syncthreads();
    const uint32_t tmem = *reinterpret_cast<volatile uint32_t*>(smem);

    for (int k = 0; k < 16; ++k) {
        const int s = k & 1;
        if (k < 15) {
            const int j = k + 1;
            if (j >= 2) mbar_wait(sb + 8 + (j & 1) * 8, (uint32_t)(((j >> 1) - 1) & 1));
            copies(j, j & 1);
            asm volatile("cp.async.wait_group 1;" ::: "memory");
        } else {
            asm volatile("cp.async.wait_group 0;" ::: "memory");
        }
        __syncthreads();
        asm volatile("fence.proxy.async.shared::cta;" ::: "memory");

        if (tid < 32 && elect_one_pred()) {
            const uint32_t base = sb + 1024 + s * OUT_STAGE;
            const uint64_t dAh = make_desc(base);
            const uint64_t dAl = make_desc(base + 32768);
            const uint64_t dBh = make_desc(base + 65536);
            const uint64_t dBl = make_desc(base + 65536 + TILE_BYTES);
#pragma unroll
            for (int s2 = 0; s2 < 2; ++s2) {
                const uint64_t ao = (uint64_t)s2 * 1024;   // +16KB in 16B units
                const uint32_t dd = tmem + s2 * 128;
#pragma unroll
                for (int ks = 0; ks < 4; ++ks) {
                    const uint32_t en0 = (k == 0 && ks == 0) ? 0u : 1u;
                    mma_f16_ss(dd, dAh + ao + ks * 2, dBh + ks * 2, IDESC_128x128, en0);
                    mma_f16_ss(dd, dAh + ao + ks * 2, dBl + ks * 2, IDESC_128x128, 1u);
                    mma_f16_ss(dd, dAl + ao + ks * 2, dBh + ks * 2, IDESC_128x128, 1u);
                }
            }
            tc_commit(sb + 8 + s * 8);
        }
    }
    mbar_wait(sb + 8, 1u);
    mbar_wait(sb + 16, 1u);
    asm volatile("tcgen05.fence::after_thread_sync;" ::: "memory");
    __syncthreads();

    const float g = gamma[0];
    if (tid < 128) {
#pragma unroll
        for (int s2 = 0; s2 < 2; ++s2) {
            const size_t base = ((size_t)b * C_ + m0 + s2 * 128 + tid) * HW_ + n0;
            for (int cb = 0; cb < 128; cb += 32) {
                uint32_t d[32];
                TCGEN05_LD_32X32B_X32(d, tmem + s2 * 128 + cb);
                asm volatile("tcgen05.wait::ld.sync.aligned;" ::: "memory");
#pragma unroll
                for (int e = 0; e < 8; ++e) {
                    const size_t gb = base + cb + e * 4;
                    float4 x4 = *reinterpret_cast<const float4*>(x + gb);
                    float4 h4 = *reinterpret_cast<const float4*>(hha + gb);
                    const float o0 = g * __uint_as_float(d[4 * e]);
                    const float o1 = g * __uint_as_float(d[4 * e + 1]);
                    const float o2 = g * __uint_as_float(d[4 * e + 2]);
                    const float o3 = g * __uint_as_float(d[4 * e + 3]);
                    *reinterpret_cast<float4*>(rgb + gb) =
                        make_float4(o0 + x4.x, o1 + x4.y, o2 + x4.z, o3 + x4.w);
                    *reinterpret_cast<float4*>(hhaout + gb) =
                        make_float4(o0 + h4.x, o1 + h4.y, o2 + h4.z, o3 + h4.w);
                }
            }
        }
    }
    __syncthreads();
    if (tid == 0) { mbar_inval(sb + 8); mbar_inval(sb + 16); }
    if (tid < 32) tc_dealloc(tmem, 256u);
#else
    const float g = gamma[0];
    for (int e = tid; e < 256 * 128; e += 256) {
        const int ml = e >> 7, nl = e & 127;
        float acc = 0.f;
        for (int j = 0; j < HW_; ++j)
            acc += recon(g_v_hi, g_v_lo, ((size_t)b * C_ + m0 + ml) * HW_ + j) *
                   recon(g_att_hi, g_att_lo, ((size_t)b * HW_ + n0 + nl) * HW_ + j);
        const size_t gb = ((size_t)b * C_ + m0 + ml) * HW_ + n0 + nl;
        rgb[gb]    = g * acc + x[gb];
        hhaout[gb] = g * acc + hha[gb];
    }
#endif
}

// ---------------------------------------------------------------------------
extern "C" void kernel_launch(void* const* d_in, const int* in_sizes, int n_in,
                              void* d_out, int out_size)
{
    const float* x     = (const float*)d_in[0];
    const float* hha   = (const float*)d_in[1];
    const float* wq    = (const float*)d_in[2];
    const float* bq    = (const float*)d_in[3];
    const float* wk    = (const float*)d_in[4];
    const float* bk    = (const float*)d_in[5];
    const float* wv    = (const float*)d_in[6];
    const float* bv    = (const float*)d_in[7];
    const float* gamma = (const float*)d_in[8];

    float* att    = (float*)d_out;                         // [32,1024,1024]
    float* rgb    = att + (size_t)B_ * HW_ * HW_;          // [32,512,32,32]
    float* hhaout = rgb + (size_t)B_ * C_ * HW_;           // [32,512,32,32]

    static bool attr_set = false;
    if (!attr_set) {
        cudaFuncSetAttribute(qkv_tc_kernel,    cudaFuncAttributeMaxDynamicSharedMemorySize, QKV_SMEM);
        cudaFuncSetAttribute(energy_tc_kernel, cudaFuncAttributeMaxDynamicSharedMemorySize, EN_SMEM);
        cudaFuncSetAttribute(out_tc_kernel,    cudaFuncAttributeMaxDynamicSharedMemorySize, OUT_SMEM);
        attr_set = true;
    }

    xsplit_kernel   <<<dim3(32, 16, 32), dim3(32, 8)>>>(x);
    wsplit_kernel   <<<WR_ * C_ / 256, 256>>>(wq, wk, wv);
    qkv_tc_kernel   <<<dim3(8, 5, 32), 256, QKV_SMEM>>>(bq, bk, bv);
    energy_tc_kernel<<<dim3(2, 8, 32), 256, EN_SMEM>>>(att);
    softmax_kernel  <<<B_ * HW_, 256>>>(att);
    out_tc_kernel   <<<dim3(8, 2, 32), 256, OUT_SMEM>>>(x, hha, gamma, rgb, hhaout);
}